// round 8
// baseline (speedup 1.0000x reference)
#include <cuda_runtime.h>

#define HW_DIM 10
#define NUM_DEV 50
#define NUM_INT 101
#define ODIM 30
#define NWARP 8
#define EPW 7                  // expert slots per warp (8*7=56, slots 50..55 padded)
#define ROW (NUM_INT * ODIM)   // 3030 floats per expert

// 8 warps, 7 expert-slots each. Pad slots clamp the address to expert 49 and
// carry a zero gate (contribute nothing). Per-warp: 7 gather LDGs, one gate
// per active lane, 7-FMA combine. One __syncthreads merge tail.
__global__ __launch_bounds__(256, 1)
void mhn_kernel(const float* __restrict__ x,
                const float* __restrict__ hw,
                const float* __restrict__ hw_emb,
                const float* __restrict__ expert_emb,
                float* __restrict__ out)
{
    const int tid  = threadIdx.x;
    const int w    = tid >> 5;
    const int lane = tid & 31;

    __shared__ __align__(16) float gs[NWARP][8];  // per-warp gates (7 valid, [7]=0)
    __shared__ float accsh[NWARP][32];            // per-warp partial outputs
    __shared__ float ssh[NWARP];                  // per-warp partial softmax sums

    // ---- Chain A root: x first; minimal idx chain ----
    const float xv  = __ldg(x);
    const int   idx = __float2int_rn(xv * (float)(NUM_INT - 1));

    // ---- Chain B loads (in flight while x resolves) ----
    float h[HW_DIM];
    {
        const float4 h0 = __ldg((const float4*)hw);
        const float4 h1 = __ldg((const float4*)(hw + 4));
        const float2 h2 = __ldg((const float2*)(hw + 8));
        h[0]=h0.x; h[1]=h0.y; h[2]=h0.z; h[3]=h0.w;
        h[4]=h1.x; h[5]=h1.y; h[6]=h1.z; h[7]=h1.w;
        h[8]=h2.x; h[9]=h2.y;
    }
    // Gate expert for this lane (lanes 0..EPW-1 own slots; others dup lane 0)
    const int slot = w * EPW + ((lane < EPW) ? lane : 0);
    const int eg   = (slot < NUM_DEV) ? slot : (NUM_DEV - 1);
    float he[HW_DIM];
    {
        const float2* p = (const float2*)(hw_emb + eg * HW_DIM);
#pragma unroll
        for (int j = 0; j < 5; ++j) { float2 t = __ldg(p + j); he[2*j] = t.x; he[2*j+1] = t.y; }
    }

    // ---- Chain A: 7 gather loads per warp (addresses clamped for pads) ----
    const int d = (lane < ODIM) ? lane : 0;
    float v[EPW];
#pragma unroll
    for (int j = 0; j < EPW; ++j) {
        int e = w * EPW + j;
        if (e >= NUM_DEV) e = NUM_DEV - 1;
        v[j] = __ldg(expert_emb + (size_t)e * ROW + (size_t)idx * ODIM + d);
    }

    // ---- Gate: one dot -> sin -> exp per lane (sin in [-1,1], no max-sub) ----
    const float inv_sqrt = 0.31622776601683794f;
    float dt0 = 0.f, dt1 = 0.f;
#pragma unroll
    for (int j = 0; j < 5; ++j) {
        dt0 = fmaf(h[2*j],   he[2*j],   dt0);
        dt1 = fmaf(h[2*j+1], he[2*j+1], dt1);
    }
    const float g = __expf(__sinf((dt0 + dt1) * inv_sqrt));

    // Publish gates: zero for pad slots and lane 7
    if (lane < 8) gs[w][lane] = (lane < EPW && slot < NUM_DEV) ? g : 0.f;
    __syncwarp();

    // ---- Per-warp combine: float4 + 3 scalar gate reads, 7 FMAs ----
    float accA = 0.f, accB = 0.f, sA = 0.f, sB = 0.f;
    {
        const float4 gq = *(const float4*)gs[w];
        accA = fmaf(gq.x, v[0], accA);  sA += gq.x;
        accB = fmaf(gq.y, v[1], accB);  sB += gq.y;
        accA = fmaf(gq.z, v[2], accA);  sA += gq.z;
        accB = fmaf(gq.w, v[3], accB);  sB += gq.w;
    }
    {
        const float g4 = gs[w][4], g5 = gs[w][5], g6 = gs[w][6];
        accA = fmaf(g4, v[4], accA);  sA += g4;
        accB = fmaf(g5, v[5], accB);  sB += g5;
        accA = fmaf(g6, v[6], accA);  sA += g6;
    }

    accsh[w][lane] = accA + accB;
    if (lane == 0) ssh[w] = sA + sB;
    __syncthreads();

    // ---- Warp 0 merges 8 partials and writes (conflict-free scalar LDS) ----
    if (tid < ODIM) {
        float num = ((accsh[0][tid] + accsh[1][tid]) + (accsh[2][tid] + accsh[3][tid]))
                  + ((accsh[4][tid] + accsh[5][tid]) + (accsh[6][tid] + accsh[7][tid]));
        float den = ((ssh[0] + ssh[1]) + (ssh[2] + ssh[3]))
                  + ((ssh[4] + ssh[5]) + (ssh[6] + ssh[7]));
        out[tid] = __fdividef(num, den);
    }
}

extern "C" void kernel_launch(void* const* d_in, const int* in_sizes, int n_in,
                              void* d_out, int out_size)
{
    const float* x          = (const float*)d_in[0];
    const float* hw         = (const float*)d_in[1];
    const float* hw_emb     = (const float*)d_in[2];
    const float* expert_emb = (const float*)d_in[3];
    float* out = (float*)d_out;

    mhn_kernel<<<1, 256>>>(x, hw, hw_emb, expert_emb, out);
}

// round 9
// speedup vs baseline: 1.4795x; 1.4795x over previous
#include <cuda_runtime.h>

#define HW_DIM 10
#define NUM_DEV 50
#define NUM_INT 101
#define ODIM 30
#define NWARP 5
#define EPW 10                 // 5 warps * 10 experts = 50 exactly, no padding
#define ROW (NUM_INT * ODIM)   // 3030 floats per expert

// 5 warps, 10 experts each (exact cover: no clamps, no pad gates).
// Per-warp: 10 gather LDGs, one gate per active lane, 10-FMA combine.
// One __syncthreads merge tail over 5 partials.
__global__ __launch_bounds__(160, 1)
void mhn_kernel(const float* __restrict__ x,
                const float* __restrict__ hw,
                const float* __restrict__ hw_emb,
                const float* __restrict__ expert_emb,
                float* __restrict__ out)
{
    const int tid  = threadIdx.x;
    const int w    = tid >> 5;
    const int lane = tid & 31;

    __shared__ __align__(16) float gs[NWARP][12];  // 10 valid gates; 48B rows (16B-aligned)
    __shared__ float accsh[NWARP][32];             // per-warp partial outputs
    __shared__ float ssh[NWARP];                   // per-warp partial softmax sums

    // ---- Chain A root: x first; minimal idx chain ----
    const float xv  = __ldg(x);
    const int   idx = __float2int_rn(xv * (float)(NUM_INT - 1));

    // ---- Chain B loads (in flight while x resolves) ----
    float h[HW_DIM];
    {
        const float4 h0 = __ldg((const float4*)hw);
        const float4 h1 = __ldg((const float4*)(hw + 4));
        const float2 h2 = __ldg((const float2*)(hw + 8));
        h[0]=h0.x; h[1]=h0.y; h[2]=h0.z; h[3]=h0.w;
        h[4]=h1.x; h[5]=h1.y; h[6]=h1.z; h[7]=h1.w;
        h[8]=h2.x; h[9]=h2.y;
    }
    // Gate expert for this lane: lanes 0..9 own experts w*10+lane (others dup lane 0)
    const int eg = w * EPW + ((lane < EPW) ? lane : 0);
    float he[HW_DIM];
    {
        const float2* p = (const float2*)(hw_emb + eg * HW_DIM);
#pragma unroll
        for (int j = 0; j < 5; ++j) { float2 t = __ldg(p + j); he[2*j] = t.x; he[2*j+1] = t.y; }
    }

    // ---- Chain A: 10 gather loads per warp (no clamps needed) ----
    const int d = (lane < ODIM) ? lane : 0;
    const float* gbase = expert_emb + (size_t)(w * EPW) * ROW + (size_t)idx * ODIM + d;
    float v[EPW];
#pragma unroll
    for (int j = 0; j < EPW; ++j)
        v[j] = __ldg(gbase + (size_t)j * ROW);

    // ---- Gate: one dot -> sin -> exp per lane (sin in [-1,1], no max-sub) ----
    const float inv_sqrt = 0.31622776601683794f;
    float dt0 = 0.f, dt1 = 0.f;
#pragma unroll
    for (int j = 0; j < 5; ++j) {
        dt0 = fmaf(h[2*j],   he[2*j],   dt0);
        dt1 = fmaf(h[2*j+1], he[2*j+1], dt1);
    }
    const float g = __expf(__sinf((dt0 + dt1) * inv_sqrt));

    if (lane < EPW) gs[w][lane] = g;
    __syncwarp();

    // ---- Per-warp combine: 2x float4 + 2 scalar gate reads, 10 FMAs ----
    float accA = 0.f, accB = 0.f, sA = 0.f, sB = 0.f;
#pragma unroll
    for (int i = 0; i < 2; ++i) {
        const float4 gq = *(const float4*)(gs[w] + 4 * i);
        accA = fmaf(gq.x, v[4*i+0], accA);  sA += gq.x;
        accB = fmaf(gq.y, v[4*i+1], accB);  sB += gq.y;
        accA = fmaf(gq.z, v[4*i+2], accA);  sA += gq.z;
        accB = fmaf(gq.w, v[4*i+3], accB);  sB += gq.w;
    }
    {
        const float g8 = gs[w][8], g9 = gs[w][9];
        accA = fmaf(g8, v[8], accA);  sA += g8;
        accB = fmaf(g9, v[9], accB);  sB += g9;
    }

    accsh[w][lane] = accA + accB;
    if (lane == 0) ssh[w] = sA + sB;
    __syncthreads();

    // ---- Warp 0 merges 5 partials and writes ----
    if (tid < ODIM) {
        const float num = ((accsh[0][tid] + accsh[1][tid])
                        +  (accsh[2][tid] + accsh[3][tid])) + accsh[4][tid];
        const float den = ((ssh[0] + ssh[1]) + (ssh[2] + ssh[3])) + ssh[4];
        out[tid] = __fdividef(num, den);
    }
}

extern "C" void kernel_launch(void* const* d_in, const int* in_sizes, int n_in,
                              void* d_out, int out_size)
{
    const float* x          = (const float*)d_in[0];
    const float* hw         = (const float*)d_in[1];
    const float* hw_emb     = (const float*)d_in[2];
    const float* expert_emb = (const float*)d_in[3];
    float* out = (float*)d_out;

    mhn_kernel<<<1, 160>>>(x, hw, hw_emb, expert_emb, out);
}